// round 9
// baseline (speedup 1.0000x reference)
#include <cuda_runtime.h>
#include <cuda_fp16.h>

#define D_IN   1024
#define D_FEAT 4096
#define DEG    4
#define RPB    8

// fp16 table (values pre-scaled by 1/32 -> ~unit variance), per degree d:
// 1024 idx x 16B. Word w of idx holds row-pair p = w ^ s(idx), s=(idx>>3)&3,
// even row in low half. Phase-1 STS.32 is conflict-free
// (bank = 4*(lane&7) + (p ^ (lane>>3)) -> 32 distinct).
// Phase-2: one LDS.128 per (feature,degree); product accumulated in half2
// (HMUL2), converted to fp32 once at the end. 32^4 folded into oscale.

__device__ ushort4 g_perm16[D_FEAT];

__global__ void pack_perm_kernel(const int* __restrict__ perm) {
    int f = blockIdx.x * 256 + threadIdx.x;
    if (f < D_FEAT) {
        g_perm16[f] = make_ushort4((unsigned short)perm[f],
                                   (unsigned short)perm[D_FEAT + f],
                                   (unsigned short)perm[2 * D_FEAT + f],
                                   (unsigned short)perm[3 * D_FEAT + f]);
    }
}

__global__ __launch_bounds__(512, 2)
void srht_kernel(const float* __restrict__ x,
                 const float* __restrict__ rad,
                 const float* __restrict__ log_ls,
                 const float* __restrict__ log_var,
                 float* __restrict__ out)
{
    extern __shared__ __align__(16) unsigned char smem_raw[];
    unsigned*     tabw  = reinterpret_cast<unsigned*>(smem_raw);       // [DEG][1024][4] half2 words
    const uint4*  tab4  = reinterpret_cast<const uint4*>(smem_raw);    // [DEG][1024]
    unsigned*     radw  = reinterpret_cast<unsigned*>(smem_raw + DEG * D_IN * RPB * 2);
    const uint4*  radw4 = reinterpret_cast<const uint4*>(radw);        // [DEG][8]

    const int tid  = threadIdx.x;
    const int wid  = tid >> 5;          // 0..15
    const int lane = tid & 31;
    const int row0 = blockIdx.x * RPB;

    // ---------------- Phase 0: build rad sign words (warps 0..3) ----------------
    if (wid < 4) {
        const float* __restrict__ rd = rad + wid * D_IN;
        #pragma unroll
        for (int k = 0; k < 32; k++) {
            float f = rd[k * 32 + lane];
            unsigned m = __ballot_sync(0xffffffffu, f < 0.0f);
            if (lane == (k & 31)) radw[wid * 32 + k] = m;
        }
    }
    __syncthreads();

    // ---------------- Phase 1: FWHT; warp = (degree, row-pair); packed STS.32 ----------------
    {
        const int d  = wid >> 2;            // 0..3
        const int p  = wid & 3;             // row pair 0..3
        const int sh = 31 - lane;           // puts sign bit 'lane' at bit 31
        const float tscale = 0.03125f;      // 1/32: keeps fp16 table ~unit variance

        unsigned h2a[16];                   // packed fp16 of even row (k, k+1 pairs)

        #pragma unroll
        for (int e = 0; e < 2; e++) {
            const int r = 2 * p + e;
            const float* __restrict__ xr = x + (size_t)(row0 + r) * D_IN;

            float v[32];                    // lane holds i = k*32 + lane
            #pragma unroll
            for (int kc = 0; kc < 8; kc++) {
                uint4 wq = radw4[d * 8 + kc];   // broadcast LDS.128: signs for k = 4kc..4kc+3
                #pragma unroll
                for (int j = 0; j < 4; j++) {
                    const int k = kc * 4 + j;
                    unsigned w = (j == 0) ? wq.x : (j == 1) ? wq.y : (j == 2) ? wq.z : wq.w;
                    unsigned xb = __float_as_uint(xr[k * 32 + lane]);
                    v[k] = __uint_as_float(xb ^ ((w << sh) & 0x80000000u));
                }
            }

            // lane-bit stages h = 1..16 via shuffle
            #pragma unroll
            for (int hb = 0; hb < 5; hb++) {
                const int h = 1 << hb;
                const bool up = (lane & h) != 0;
                #pragma unroll
                for (int k = 0; k < 32; k++) {
                    float o = __shfl_xor_sync(0xffffffffu, v[k], h);
                    v[k] = up ? (o - v[k]) : (v[k] + o);
                }
            }
            // register-bit stages h = 32..512
            #pragma unroll
            for (int mb = 0; mb < 5; mb++) {
                const int m = 1 << mb;
                #pragma unroll
                for (int k = 0; k < 32; k++) {
                    if ((k & m) == 0) {
                        float a = v[k], b = v[k + m];
                        v[k] = a + b;  v[k + m] = a - b;
                    }
                }
            }

            if (e == 0) {
                // stash even row as packed fp16 (scaled)
                #pragma unroll
                for (int j = 0; j < 16; j++) {
                    __half2 hp = __floats2half2_rn(v[2*j] * tscale, v[2*j+1] * tscale);
                    h2a[j] = *reinterpret_cast<unsigned*>(&hp);
                }
            } else {
                // combine with odd row and store one half2 word per i (conflict-free)
                const int sp = p ^ ((lane >> 3) & 3);   // slot w for this warp's i's
                #pragma unroll
                for (int k = 0; k < 32; k++) {
                    const int i = k * 32 + lane;
                    unsigned lo = (k & 1) ? (h2a[k >> 1] >> 16) : (h2a[k >> 1] & 0xffffu);
                    unsigned hb = (unsigned)__half_as_ushort(__float2half_rn(v[k] * tscale));
                    tabw[d * 4096 + i * 4 + sp] = lo | (hb << 16);
                }
            }
        }
    }
    __syncthreads();

    // ---------------- Phase 2: gather (LDS.128/lane) + half2 product + stores ----------------
    // oscale folds exp(log_var/2), 1/sqrt(D_FEAT)=1/64, inv_ls^4, and 32^4 table scaling
    const float oscale = expf(0.5f * log_var[0] - 4.0f * log_ls[0]) * 16384.0f;
    float* __restrict__ ob = out + (size_t)row0 * D_FEAT;

    #pragma unroll
    for (int it = 0; it < 8; it++) {
        const int f = it * 512 + wid * 32 + lane;   // this lane's feature

        const ushort4 pp = g_perm16[f];             // one LDG.64: all 4 degree-indices
        const int idxs[4] = { pp.x, pp.y, pp.z, pp.w };

        unsigned acc0, acc1, acc2, acc3;            // half2 row-pair accumulators

        #pragma unroll
        for (int dd = 0; dd < DEG; dd++) {
            const int idx = idxs[dd];
            uint4 h = tab4[dd * 1024 + idx];        // whole idx: 8 rows fp16
            const int s = (idx >> 3) & 3;
            // branch-free un-swizzle: g[w] = h[w ^ s]
            unsigned hx = (s & 1) ? h.y : h.x;
            unsigned hy = (s & 1) ? h.x : h.y;
            unsigned hz = (s & 1) ? h.w : h.z;
            unsigned hw = (s & 1) ? h.z : h.w;
            unsigned g0 = (s & 2) ? hz : hx;
            unsigned g1 = (s & 2) ? hw : hy;
            unsigned g2 = (s & 2) ? hx : hz;
            unsigned g3 = (s & 2) ? hy : hw;

            if (dd == 0) {
                acc0 = g0; acc1 = g1; acc2 = g2; acc3 = g3;
            } else {
                __half2 a;
                a = __hmul2(*(__half2*)&acc0, *(__half2*)&g0); acc0 = *(unsigned*)&a;
                a = __hmul2(*(__half2*)&acc1, *(__half2*)&g1); acc1 = *(unsigned*)&a;
                a = __hmul2(*(__half2*)&acc2, *(__half2*)&g2); acc2 = *(unsigned*)&a;
                a = __hmul2(*(__half2*)&acc3, *(__half2*)&g3); acc3 = *(unsigned*)&a;
            }
        }

        float2 f0 = __half22float2(*(__half2*)&acc0);
        float2 f1 = __half22float2(*(__half2*)&acc1);
        float2 f2 = __half22float2(*(__half2*)&acc2);
        float2 f3 = __half22float2(*(__half2*)&acc3);

        // 8 fully-coalesced 128B row stores
        ob[0 * D_FEAT + f] = f0.x * oscale;
        ob[1 * D_FEAT + f] = f0.y * oscale;
        ob[2 * D_FEAT + f] = f1.x * oscale;
        ob[3 * D_FEAT + f] = f1.y * oscale;
        ob[4 * D_FEAT + f] = f2.x * oscale;
        ob[5 * D_FEAT + f] = f2.y * oscale;
        ob[6 * D_FEAT + f] = f3.x * oscale;
        ob[7 * D_FEAT + f] = f3.y * oscale;
    }
}

extern "C" void kernel_launch(void* const* d_in, const int* in_sizes, int n_in,
                              void* d_out, int out_size)
{
    const float* x   = (const float*)d_in[0];
    const float* rad = (const float*)d_in[1];
    const int*   pm  = (const int*)d_in[2];
    const float* lls = (const float*)d_in[3];
    const float* lv  = (const float*)d_in[4];
    float* out = (float*)d_out;

    const int rows = in_sizes[0] / D_IN;                            // 16384
    const int smem = DEG * D_IN * RPB * 2 + 512;                    // 66048 B

    pack_perm_kernel<<<D_FEAT / 256, 256>>>(pm);

    cudaFuncSetAttribute(srht_kernel,
                         cudaFuncAttributeMaxDynamicSharedMemorySize, smem);
    srht_kernel<<<rows / RPB, 512, smem>>>(x, rad, lls, lv, out);
}

// round 10
// speedup vs baseline: 1.0084x; 1.0084x over previous
#include <cuda_runtime.h>
#include <cuda_fp16.h>

#define D_IN   1024
#define D_FEAT 4096
#define DEG    4
#define RPB    4          // rows per block (small blocks -> 4 async blocks/SM)

// fp16 table, per degree d: 1024 idx x 8B (4 rows). Word w of idx holds
// row-pair p = w ^ s(idx), s = (idx>>4)&1, even row in low half.
//  - phase-1 STS.32 (warp owns (d, pair p), lanes sweep i=k*32+lane):
//    bank = (2*lane + (p ^ (lane>>4))) mod 32 -> 32 distinct: conflict-free.
//  - phase-2 gather: one LDS.64 per (feature, degree) fetches all 4 rows.
// rad (+-1) lives as sign bitmask words; perm repacked to ushort4 per launch.
// Rationale: 4 independently-phased blocks/SM interleave FWHT(compute) and
// gather(L1) phases, raising average L1-crossbar utilization.

__device__ ushort4 g_perm16[D_FEAT];

__global__ void pack_perm_kernel(const int* __restrict__ perm) {
    int f = blockIdx.x * 256 + threadIdx.x;
    if (f < D_FEAT) {
        g_perm16[f] = make_ushort4((unsigned short)perm[f],
                                   (unsigned short)perm[D_FEAT + f],
                                   (unsigned short)perm[2 * D_FEAT + f],
                                   (unsigned short)perm[3 * D_FEAT + f]);
    }
}

__global__ __launch_bounds__(256, 4)
void srht_kernel(const float* __restrict__ x,
                 const float* __restrict__ rad,
                 const float* __restrict__ log_ls,
                 const float* __restrict__ log_var,
                 float* __restrict__ out)
{
    extern __shared__ __align__(16) unsigned char smem_raw[];
    unsigned*     tabw  = reinterpret_cast<unsigned*>(smem_raw);       // [DEG][1024][2] half2 words
    const uint2*  tab2  = reinterpret_cast<const uint2*>(smem_raw);    // [DEG][1024]
    unsigned*     radw  = reinterpret_cast<unsigned*>(smem_raw + DEG * D_IN * RPB * 2);
    const uint4*  radw4 = reinterpret_cast<const uint4*>(radw);        // [DEG][8]

    const int tid  = threadIdx.x;
    const int wid  = tid >> 5;          // 0..7
    const int lane = tid & 31;
    const int row0 = blockIdx.x * RPB;

    // ---------------- Phase 0: build rad sign words (warps 0..3) ----------------
    if (wid < 4) {
        const float* __restrict__ rd = rad + wid * D_IN;
        #pragma unroll
        for (int k = 0; k < 32; k++) {
            float f = rd[k * 32 + lane];
            unsigned m = __ballot_sync(0xffffffffu, f < 0.0f);
            if (lane == (k & 31)) radw[wid * 32 + k] = m;
        }
    }
    __syncthreads();

    // ---------------- Phase 1: FWHT; warp = (degree, row-pair); packed STS.32 ----------------
    {
        const int d  = wid >> 1;            // 0..3
        const int p  = wid & 1;             // row pair 0..1
        const int sh = 31 - lane;           // puts sign bit 'lane' at bit 31

        unsigned h2a[16];                   // packed fp16 of even row (k, k+1 pairs)

        #pragma unroll
        for (int e = 0; e < 2; e++) {
            const int r = 2 * p + e;
            const float* __restrict__ xr = x + (size_t)(row0 + r) * D_IN;

            float v[32];                    // lane holds i = k*32 + lane
            #pragma unroll
            for (int kc = 0; kc < 8; kc++) {
                uint4 wq = radw4[d * 8 + kc];   // broadcast LDS.128: signs for k = 4kc..4kc+3
                #pragma unroll
                for (int j = 0; j < 4; j++) {
                    const int k = kc * 4 + j;
                    unsigned w = (j == 0) ? wq.x : (j == 1) ? wq.y : (j == 2) ? wq.z : wq.w;
                    unsigned xb = __float_as_uint(xr[k * 32 + lane]);
                    v[k] = __uint_as_float(xb ^ ((w << sh) & 0x80000000u));
                }
            }

            // lane-bit stages h = 1..16 via shuffle
            #pragma unroll
            for (int hb = 0; hb < 5; hb++) {
                const int h = 1 << hb;
                const bool up = (lane & h) != 0;
                #pragma unroll
                for (int k = 0; k < 32; k++) {
                    float o = __shfl_xor_sync(0xffffffffu, v[k], h);
                    v[k] = up ? (o - v[k]) : (v[k] + o);
                }
            }
            // register-bit stages h = 32..512
            #pragma unroll
            for (int mb = 0; mb < 5; mb++) {
                const int m = 1 << mb;
                #pragma unroll
                for (int k = 0; k < 32; k++) {
                    if ((k & m) == 0) {
                        float a = v[k], b = v[k + m];
                        v[k] = a + b;  v[k + m] = a - b;
                    }
                }
            }

            if (e == 0) {
                // stash even row as packed fp16
                #pragma unroll
                for (int j = 0; j < 16; j++) {
                    __half2 hp = __floats2half2_rn(v[2*j], v[2*j+1]);
                    h2a[j] = *reinterpret_cast<unsigned*>(&hp);
                }
            } else {
                // combine with odd row, one half2 word per i (conflict-free)
                const int sp = p ^ ((lane >> 4) & 1);   // slot for this warp's i's
                #pragma unroll
                for (int k = 0; k < 32; k++) {
                    const int i = k * 32 + lane;
                    unsigned lo = (k & 1) ? (h2a[k >> 1] >> 16) : (h2a[k >> 1] & 0xffffu);
                    unsigned hb = (unsigned)__half_as_ushort(__float2half_rn(v[k]));
                    tabw[d * 2048 + i * 2 + sp] = lo | (hb << 16);
                }
            }
        }
    }
    __syncthreads();

    // ---------------- Phase 2: gather (LDS.64/lane) + product + coalesced stores ----------------
    // oscale folds exp(log_var/2), 1/sqrt(D_FEAT), inv_lengthscale^DEG
    const float oscale = expf(0.5f * log_var[0] - 4.0f * log_ls[0]) * (1.0f / 64.0f);
    float* __restrict__ ob = out + (size_t)row0 * D_FEAT;

    #pragma unroll
    for (int it = 0; it < 16; it++) {
        const int f = it * 256 + wid * 32 + lane;   // this lane's feature

        const ushort4 pp = g_perm16[f];             // one LDG.64: all 4 degree-indices
        const int idxs[4] = { pp.x, pp.y, pp.z, pp.w };

        float a0 = oscale, a1 = oscale, a2 = oscale, a3 = oscale;

        #pragma unroll
        for (int dd = 0; dd < DEG; dd++) {
            const int idx = idxs[dd];
            uint2 h = tab2[dd * 1024 + idx];        // whole idx: 4 rows fp16
            const int s = (idx >> 4) & 1;
            unsigned g0 = s ? h.y : h.x;            // pair 0 (rows 0,1)
            unsigned g1 = s ? h.x : h.y;            // pair 1 (rows 2,3)

            float2 f0 = __half22float2(*reinterpret_cast<__half2*>(&g0));
            float2 f1 = __half22float2(*reinterpret_cast<__half2*>(&g1));
            a0 *= f0.x;  a1 *= f0.y;
            a2 *= f1.x;  a3 *= f1.y;
        }

        // 4 fully-coalesced 128B row stores
        ob[0 * D_FEAT + f] = a0;
        ob[1 * D_FEAT + f] = a1;
        ob[2 * D_FEAT + f] = a2;
        ob[3 * D_FEAT + f] = a3;
    }
}

extern "C" void kernel_launch(void* const* d_in, const int* in_sizes, int n_in,
                              void* d_out, int out_size)
{
    const float* x   = (const float*)d_in[0];
    const float* rad = (const float*)d_in[1];
    const int*   pm  = (const int*)d_in[2];
    const float* lls = (const float*)d_in[3];
    const float* lv  = (const float*)d_in[4];
    float* out = (float*)d_out;

    const int rows = in_sizes[0] / D_IN;                            // 16384
    const int smem = DEG * D_IN * RPB * 2 + 512;                    // 33280 B

    pack_perm_kernel<<<D_FEAT / 256, 256>>>(pm);

    cudaFuncSetAttribute(srht_kernel,
                         cudaFuncAttributeMaxDynamicSharedMemorySize, smem);
    srht_kernel<<<rows / RPB, 256, smem>>>(x, rad, lls, lv, out);
}